// round 16
// baseline (speedup 1.0000x reference)
#include <cuda_runtime.h>
#include <cuda_fp16.h>
#include <math.h>
#include <stdint.h>

#define B_      16
#define NQ_     300
#define C_      256
#define H_      8
#define L_      4
#define P_      4
#define DH_     32
#define DFFN_   1024
#define LEN_IN_ 19947
#define MROWS   (B_*NQ_)        // 4800
#define MVAL    (B_*LEN_IN_)    // 319152
#define VCHUNKS 4
#define BPC     (B_/VCHUNKS)    // 4 batches per chunk
#define MCH     (BPC*LEN_IN_)   // 79788 rows per value chunk

// ---------------- scratch (device globals; no allocation allowed) ----------
__device__ float  g_q     [MROWS*C_];
__device__ float  g_qk    [MROWS*2*C_];
__device__ float  g_vp    [MROWS*C_];
__device__ float  g_sa    [MROWS*C_];
__device__ float  g_proj  [MROWS*C_];
__device__ float  g_tgt2  [MROWS*C_];
__device__ float  g_query2[MROWS*C_];
__device__ float  g_off   [MROWS*C_];
__device__ float  g_awl   [MROWS*128];
__device__ float  g_cain  [MROWS*C_];
__device__ float  g_tgt3  [MROWS*C_];
__device__ float  g_ffn   [MROWS*DFFN_];
__device__ __half g_value [81702912];   // MVAL * 256 halfs = 163 MB

// ===========================================================================
// tf32 tensor-core NT GEMM v3: BM=64, BN=128, 3-stage cp.async ring.
// 256 threads = 8 warps (2x4), warp tile 32x32.
// C[m,n] = sum_k A[m,k]*W[n,k] + bias[n].
// ===========================================================================
#define GEMM_ASTG  (64 * 36)
#define GEMM_WSTG  (128 * 36)
#define GEMM_STG   (GEMM_ASTG + GEMM_WSTG)
#define GEMM_SMEM  (3 * GEMM_STG * 4)               // 82944 B

__device__ __forceinline__ void cp_async16(uint32_t daddr, const void* src, int sz) {
    asm volatile("cp.async.cg.shared.global [%0], [%1], 16, %2;"
                 :: "r"(daddr), "l"(src), "r"(sz));
}
__device__ __forceinline__ void cp_commit() {
    asm volatile("cp.async.commit_group;");
}
template<int N>
__device__ __forceinline__ void cp_wait() {
    asm volatile("cp.async.wait_group %0;" :: "n"(N));
}

template<int RELU, int HOUT>
__global__ __launch_bounds__(256)
void gemm_tf32(const float* __restrict__ A, const float* __restrict__ W,
               const float* __restrict__ bias, void* __restrict__ Cv,
               int M, int N, int K)
{
    extern __shared__ __align__(16) uint32_t gsm[];

    const int tid  = threadIdx.x;
    const int lane = tid & 31;
    const int warp = tid >> 5;
    const int wm   = warp >> 2;
    const int wn   = warp & 3;
    const int bm   = blockIdx.y * 64;
    const int bn   = blockIdx.x * 128;

    const int srow = tid >> 3;
    const int sk4  = (tid & 7) * 4;

    float acc[2][4][4];
#pragma unroll
    for (int i = 0; i < 2; i++)
#pragma unroll
        for (int j = 0; j < 4; j++)
#pragma unroll
            for (int r = 0; r < 4; r++) acc[i][j][r] = 0.f;

    const int grp = lane >> 2;
    const int qid = lane & 3;

    const int KT = K >> 5;

    auto prefetch = [&](int s, int kt) {
        int k0 = kt * 32;
        uint32_t abase = __cvta_generic_to_shared(gsm + s * GEMM_STG);
        uint32_t wbase = abase + GEMM_ASTG * 4;
#pragma unroll
        for (int it = 0; it < 2; it++) {
            int row = srow + it * 32;
            int gr = bm + row;
            cp_async16(abase + (row * 36 + sk4) * 4,
                       A + (size_t)gr * K + k0 + sk4, (gr < M) ? 16 : 0);
        }
#pragma unroll
        for (int it = 0; it < 4; it++) {
            int row = srow + it * 32;
            int gw = bn + row;
            cp_async16(wbase + (row * 36 + sk4) * 4,
                       W + (size_t)gw * K + k0 + sk4, 16);
        }
        cp_commit();
    };

    prefetch(0, 0);
    if (KT > 1) prefetch(1, 1);

    int stage = 0;
    for (int kt = 0; kt < KT; kt++) {
        if (kt + 2 < KT) {
            prefetch((stage + 2) % 3, kt + 2);
            cp_wait<2>();
        } else if (kt + 1 < KT) {
            cp_wait<1>();
        } else {
            cp_wait<0>();
        }
        __syncthreads();

        const uint32_t* Asl = gsm + stage * GEMM_STG;
        const uint32_t* Wsl = Asl + GEMM_ASTG;
#pragma unroll
        for (int ks = 0; ks < 4; ks++) {
            const int kc = ks * 8 + qid;
            uint32_t af[2][4];
#pragma unroll
            for (int i = 0; i < 2; i++) {
                int mb = wm * 32 + i * 16 + grp;
                af[i][0] = Asl[mb * 36 + kc];
                af[i][1] = Asl[(mb + 8) * 36 + kc];
                af[i][2] = Asl[mb * 36 + kc + 4];
                af[i][3] = Asl[(mb + 8) * 36 + kc + 4];
            }
            uint32_t bf[4][2];
#pragma unroll
            for (int j = 0; j < 4; j++) {
                int nb = wn * 32 + j * 8 + grp;
                bf[j][0] = Wsl[nb * 36 + kc];
                bf[j][1] = Wsl[nb * 36 + kc + 4];
            }
#pragma unroll
            for (int i = 0; i < 2; i++)
#pragma unroll
                for (int j = 0; j < 4; j++) {
                    asm volatile(
                        "mma.sync.aligned.m16n8k8.row.col.f32.tf32.tf32.f32 "
                        "{%0,%1,%2,%3}, {%4,%5,%6,%7}, {%8,%9}, {%0,%1,%2,%3};"
                        : "+f"(acc[i][j][0]), "+f"(acc[i][j][1]),
                          "+f"(acc[i][j][2]), "+f"(acc[i][j][3])
                        : "r"(af[i][0]), "r"(af[i][1]), "r"(af[i][2]), "r"(af[i][3]),
                          "r"(bf[j][0]), "r"(bf[j][1]));
                }
        }
        __syncthreads();
        stage = (stage + 1) % 3;
    }

    // ---- epilogue ----
    float*  Cf = (float*)Cv;
    __half* Ch = (__half*)Cv;
#pragma unroll
    for (int j = 0; j < 4; j++) {
        int cc = bn + wn * 32 + j * 8 + qid * 2;
        float b0 = bias[cc], b1 = bias[cc + 1];
#pragma unroll
        for (int i = 0; i < 2; i++) {
            int r0 = bm + wm * 32 + i * 16 + grp;
            float v0 = acc[i][j][0] + b0;
            float v1 = acc[i][j][1] + b1;
            float v2 = acc[i][j][2] + b0;
            float v3 = acc[i][j][3] + b1;
            if (RELU) {
                v0 = fmaxf(v0, 0.f); v1 = fmaxf(v1, 0.f);
                v2 = fmaxf(v2, 0.f); v3 = fmaxf(v3, 0.f);
            }
            if (HOUT) {
                if (r0 < M)
                    *(__half2*)(Ch + (size_t)r0 * N + cc) = __floats2half2_rn(v0, v1);
                if (r0 + 8 < M)
                    *(__half2*)(Ch + (size_t)(r0 + 8) * N + cc) = __floats2half2_rn(v2, v3);
            } else {
                if (r0 < M)
                    *(float2*)(Cf + (size_t)r0 * N + cc) = make_float2(v0, v1);
                if (r0 + 8 < M)
                    *(float2*)(Cf + (size_t)(r0 + 8) * N + cc) = make_float2(v2, v3);
            }
        }
    }
}

// ---------------- elementwise add -----------------------------------------
__global__ void add_kernel(const float* __restrict__ a, const float* __restrict__ b,
                           float* __restrict__ o, int n)
{
    int i = blockIdx.x * blockDim.x + threadIdx.x;
    if (i < n) o[i] = a[i] + b[i];
}

// ---------------- fused self-attention v6: 2 queries/warp, no-shfl PV ------
#define ATTN_KS_   (300*36)
#define ATTN_VT_   (32*300)
#define ATTN_WS_   (16*304)
#define ATTN_SMEM  ((ATTN_KS_ + ATTN_VT_ + ATTN_WS_) * 4)   // 101056 B
__global__ __launch_bounds__(256)
void attn_kernel(const float* __restrict__ qk, const float* __restrict__ vp,
                 float* __restrict__ sa)
{
    extern __shared__ float smem[];
    float* Ks = smem;                       // [300][36]
    float* Vt = smem + ATTN_KS_;            // [32][300]
    float* Wb = smem + ATTN_KS_ + ATTN_VT_; // [16][304]

    int bh = blockIdx.x;
    int b = bh >> 3, h = bh & 7;
    int qc = blockIdx.y;
    int wid = threadIdx.x >> 5, lane = threadIdx.x & 31;
    const float scale = 0.1767766952966369f;
    const float* kbase = qk + (size_t)b * NQ_ * 512 + 256 + h * 32;
    const float* vbase = vp + (size_t)b * NQ_ * 256 + h * 32;

    for (int idx = threadIdx.x; idx < NQ_ * 32; idx += 256) {
        int row = idx >> 5, d = idx & 31;
        Ks[row * 36 + d]  = kbase[(size_t)row * 512 + d];
        Vt[d * 300 + row] = vbase[(size_t)row * 256 + d];
    }
    __syncthreads();

    float* wsp0 = Wb + (wid * 2) * 304;
    float* wsp1 = wsp0 + 304;
    const float* vtp = Vt + lane * 300;

    const int q_end = qc * 100 + 100;
    for (int q0 = qc * 100 + wid * 2; q0 < q_end; q0 += 16) {
        const float* qrow0 = qk + (size_t)(b * NQ_ + q0) * 512 + h * 32;
        const float* qrow1 = qrow0 + 512;
        float qr0[32], qr1[32];
#pragma unroll
        for (int i = 0; i < 8; i++) {
            float4 t0 = *(const float4*)(qrow0 + i * 4);
            float4 t1 = *(const float4*)(qrow1 + i * 4);
            qr0[i*4] = t0.x; qr0[i*4+1] = t0.y; qr0[i*4+2] = t0.z; qr0[i*4+3] = t0.w;
            qr1[i*4] = t1.x; qr1[i*4+1] = t1.y; qr1[i*4+2] = t1.z; qr1[i*4+3] = t1.w;
        }
        float w0reg[10], w1reg[10];
#pragma unroll
        for (int kb = 0; kb < 10; kb++) {
            int k = kb * 32 + lane;
            float s0 = -1e30f, s1 = -1e30f;
            if (k < NQ_) {
                s0 = 0.f; s1 = 0.f;
                const float* kr = Ks + k * 36;
#pragma unroll
                for (int i = 0; i < 8; i++) {
                    float4 t = *(const float4*)(kr + i * 4);
                    s0 += qr0[i*4]*t.x + qr0[i*4+1]*t.y + qr0[i*4+2]*t.z + qr0[i*4+3]*t.w;
                    s1 += qr1[i*4]*t.x + qr1[i*4+1]*t.y + qr1[i*4+2]*t.z + qr1[i*4+3]*t.w;
                }
                s0 *= scale; s1 *= scale;
            }
            w0reg[kb] = s0; w1reg[kb] = s1;
        }
        float m0 = -1e30f, m1 = -1e30f;
#pragma unroll
        for (int kb = 0; kb < 10; kb++) {
            m0 = fmaxf(m0, w0reg[kb]);
            m1 = fmaxf(m1, w1reg[kb]);
        }
#pragma unroll
        for (int off = 16; off; off >>= 1) {
            m0 = fmaxf(m0, __shfl_xor_sync(0xffffffffu, m0, off));
            m1 = fmaxf(m1, __shfl_xor_sync(0xffffffffu, m1, off));
        }
        float ss0 = 0.f, ss1 = 0.f;
#pragma unroll
        for (int kb = 0; kb < 10; kb++) {
            float e0 = __expf(w0reg[kb] - m0);
            float e1 = __expf(w1reg[kb] - m1);
            w0reg[kb] = e0; w1reg[kb] = e1;
            ss0 += e0; ss1 += e1;
        }
#pragma unroll
        for (int off = 16; off; off >>= 1) {
            ss0 += __shfl_xor_sync(0xffffffffu, ss0, off);
            ss1 += __shfl_xor_sync(0xffffffffu, ss1, off);
        }
        float inv0 = 1.f / ss0, inv1 = 1.f / ss1;

#pragma unroll
        for (int kb = 0; kb < 10; kb++) {
            int kk = kb * 32 + lane;
            if (kk < NQ_) {
                wsp0[kk] = w0reg[kb] * inv0;
                wsp1[kk] = w1reg[kb] * inv1;
            }
        }
        __syncwarp();

        float a00 = 0.f, a01 = 0.f, a02 = 0.f, a03 = 0.f;
        float a10 = 0.f, a11 = 0.f, a12 = 0.f, a13 = 0.f;
#pragma unroll
        for (int k = 0; k < 300; k += 4) {
            float4 v  = *(const float4*)(vtp + k);
            float4 w0 = *(const float4*)(wsp0 + k);
            float4 w1 = *(const float4*)(wsp1 + k);
            a00 += w0.x * v.x; a01 += w0.y * v.y;
            a02 += w0.z * v.z; a03 += w0.w * v.w;
            a10 += w1.x * v.x; a11 += w1.y * v.y;
            a12 += w1.z * v.z; a13 += w1.w * v.w;
        }
        float acc0 = (a00 + a01) + (a02 + a03);
        float acc1 = (a10 + a11) + (a12 + a13);
        sa[(size_t)(b * NQ_ + q0) * 256 + h * 32 + lane]     = acc0;
        sa[(size_t)(b * NQ_ + q0 + 1) * 256 + h * 32 + lane] = acc1;
        __syncwarp();
    }
}

// ---------------- residual + LayerNorm (warp per row of 256) --------------
__global__ __launch_bounds__(256)
void ln_res(const float* __restrict__ x, const float* __restrict__ y,
            const float* __restrict__ gam, const float* __restrict__ bet,
            const float* __restrict__ qpos, float* __restrict__ out,
            float* __restrict__ qout)
{
    int w = threadIdx.x >> 5, lane = threadIdx.x & 31;
    int row = blockIdx.x * 8 + w;
    if (row >= MROWS) return;
    const float* xr = x + (size_t)row * 256;
    const float* yr = y + (size_t)row * 256;
    float v[8];
#pragma unroll
    for (int i = 0; i < 8; i++) { int c = i*32 + lane; v[i] = xr[c] + yr[c]; }
    float s = 0.f;
#pragma unroll
    for (int i = 0; i < 8; i++) s += v[i];
#pragma unroll
    for (int off = 16; off; off >>= 1) s += __shfl_xor_sync(0xffffffffu, s, off);
    float mean = s * (1.f / 256.f);
    float vs = 0.f;
#pragma unroll
    for (int i = 0; i < 8; i++) { float d = v[i] - mean; vs += d * d; }
#pragma unroll
    for (int off = 16; off; off >>= 1) vs += __shfl_xor_sync(0xffffffffu, vs, off);
    float rstd = rsqrtf(vs * (1.f / 256.f) + 1e-5f);
#pragma unroll
    for (int i = 0; i < 8; i++) {
        int c = i*32 + lane;
        float o = (v[i] - mean) * rstd * gam[c] + bet[c];
        out[(size_t)row * 256 + c] = o;
        if (qout) qout[(size_t)row * 256 + c] = o + qpos[(size_t)row * 256 + c];
    }
}

// ---------------- loc + attention-weight softmax (writes outputs 2 & 3) ---
__global__ __launch_bounds__(128)
void locaw_kernel(const float* __restrict__ off, const float* __restrict__ awl,
                  const float* __restrict__ refp, float* __restrict__ out_loc,
                  float* __restrict__ out_aw)
{
    int bq = blockIdx.x;
    int tid = threadIdx.x;
    int h = tid >> 4, lp = tid & 15, l = lp >> 2;

    float logit = awl[(size_t)bq * 128 + tid];
    float m = logit;
#pragma unroll
    for (int s = 8; s; s >>= 1)
        m = fmaxf(m, __shfl_xor_sync(0xffffffffu, m, s, 16));
    float e = __expf(logit - m);
    float ssum = e;
#pragma unroll
    for (int s = 8; s; s >>= 1)
        ssum += __shfl_xor_sync(0xffffffffu, ssum, s, 16);
    out_aw[(size_t)bq * 128 + tid] = e / ssum;

    float ox = off[(size_t)bq * 256 + h * 32 + lp * 2];
    float oy = off[(size_t)bq * 256 + h * 32 + lp * 2 + 1];
    float rx = refp[(size_t)bq * 8 + l * 2];
    float ry = refp[(size_t)bq * 8 + l * 2 + 1];
    float wlx = (l == 0) ? 150.f : (l == 1) ? 75.f : (l == 2) ? 38.f : 19.f;
    float wly = (l == 0) ? 100.f : (l == 1) ? 50.f : (l == 2) ? 25.f : 13.f;
    out_loc[((size_t)bq * 128 + tid) * 2]     = rx + ox / wlx;
    out_loc[((size_t)bq * 128 + tid) * 2 + 1] = ry + oy / wly;
}

// ---------------- deformable bilinear sampling (fp16 value, chunked) ------
// blk0: block-index offset so a partial launch covers bq in
// [blk0, blk0 + gridDim.x) with identical per-block work as the full launch.
__global__ __launch_bounds__(256)
void sample_kernel(const __half* __restrict__ value, const float* __restrict__ loc,
                   const float* __restrict__ aw, float* __restrict__ cain, int blk0)
{
    int widx = (blockIdx.x + blk0) * 8 + (threadIdx.x >> 5);
    int lane = threadIdx.x & 31;
    int h = widx & 7;
    int bq = widx >> 3;
    int b = bq / NQ_;

    const int HlA[4] = {100, 50, 25, 13};
    const int WlA[4] = {150, 75, 38, 19};
    const int stA[4] = {0, 15000, 18750, 19700};

    const float* locp = loc + (size_t)widx * 32;
    const float* awp  = aw  + (size_t)widx * 16;
    const __half* vb  = value + (size_t)b * LEN_IN_ * 256 + h * 32 + lane;

    float acc = 0.f;
#pragma unroll
    for (int l = 0; l < 4; l++) {
        const int Hl = HlA[l], Wl = WlA[l];
        const __half* base = vb + (size_t)stA[l] * 256;
#pragma unroll
        for (int p = 0; p < 4; p++) {
            int lp = l * 4 + p;
            float wgt = awp[lp];
            float lx = locp[lp * 2], ly = locp[lp * 2 + 1];
            float ix = lx * (float)Wl - 0.5f;
            float iy = ly * (float)Hl - 0.5f;
            float x0f = floorf(ix), y0f = floorf(iy);
            float wx = ix - x0f, wy = iy - y0f;
            int x0 = (int)x0f, y0 = (int)y0f;
            int x1 = x0 + 1, y1 = y0 + 1;
            bool vx0 = (x0 >= 0) && (x0 < Wl);
            bool vx1 = (x1 >= 0) && (x1 < Wl);
            bool vy0 = (y0 >= 0) && (y0 < Hl);
            bool vy1 = (y1 >= 0) && (y1 < Hl);
            float v00 = 0.f, v10 = 0.f, v01 = 0.f, v11 = 0.f;
            if (vx0 && vy0) v00 = __half2float(base[(size_t)(y0 * Wl + x0) * 256]);
            if (vx1 && vy0) v10 = __half2float(base[(size_t)(y0 * Wl + x1) * 256]);
            if (vx0 && vy1) v01 = __half2float(base[(size_t)(y1 * Wl + x0) * 256]);
            if (vx1 && vy1) v11 = __half2float(base[(size_t)(y1 * Wl + x1) * 256]);
            float s = (1.f - wx) * (1.f - wy) * v00 + wx * (1.f - wy) * v10
                    + (1.f - wx) * wy * v01 + wx * wy * v11;
            acc += wgt * s;
        }
    }
    cain[(size_t)bq * 256 + h * 32 + lane] = acc;
}

// ---------------------------------------------------------------------------
extern "C" void kernel_launch(void* const* d_in, const int* in_sizes, int n_in,
                              void* d_out, int out_size)
{
    const float* tgt   = (const float*)d_in[0];
    const float* qpos  = (const float*)d_in[1];
    const float* refp  = (const float*)d_in[2];
    const float* src   = (const float*)d_in[3];
    const float* w_in  = (const float*)d_in[7];
    const float* b_in  = (const float*)d_in[8];
    const float* w_out = (const float*)d_in[9];
    const float* b_out = (const float*)d_in[10];
    const float* gn2   = (const float*)d_in[11];
    const float* bn2   = (const float*)d_in[12];
    const float* w_v   = (const float*)d_in[13];
    const float* b_v   = (const float*)d_in[14];
    const float* w_off = (const float*)d_in[15];
    const float* b_off = (const float*)d_in[16];
    const float* w_aw  = (const float*)d_in[17];
    const float* b_aw  = (const float*)d_in[18];
    const float* w_o   = (const float*)d_in[19];
    const float* b_o   = (const float*)d_in[20];
    const float* gn1   = (const float*)d_in[21];
    const float* bn1   = (const float*)d_in[22];
    const float* w1    = (const float*)d_in[23];
    const float* b1    = (const float*)d_in[24];
    const float* w2    = (const float*)d_in[25];
    const float* b2    = (const float*)d_in[26];
    const float* gn3   = (const float*)d_in[27];
    const float* bn3   = (const float*)d_in[28];

    float* out_tgt = (float*)d_out;                    // B*NQ*C   = 1228800
    float* out_loc = out_tgt + 1228800;                // B*NQ*H*L*P*2 = 1228800
    float* out_aw  = out_loc + 1228800;                // B*NQ*H*L*P   = 614400

    float *p_q, *p_qk, *p_vp, *p_sa, *p_proj, *p_tgt2, *p_query2;
    float *p_off, *p_awl, *p_cain, *p_tgt3, *p_ffn;
    __half* p_value;
    cudaGetSymbolAddress((void**)&p_q,      g_q);
    cudaGetSymbolAddress((void**)&p_qk,     g_qk);
    cudaGetSymbolAddress((void**)&p_vp,     g_vp);
    cudaGetSymbolAddress((void**)&p_sa,     g_sa);
    cudaGetSymbolAddress((void**)&p_proj,   g_proj);
    cudaGetSymbolAddress((void**)&p_tgt2,   g_tgt2);
    cudaGetSymbolAddress((void**)&p_query2, g_query2);
    cudaGetSymbolAddress((void**)&p_off,    g_off);
    cudaGetSymbolAddress((void**)&p_awl,    g_awl);
    cudaGetSymbolAddress((void**)&p_cain,   g_cain);
    cudaGetSymbolAddress((void**)&p_tgt3,   g_tgt3);
    cudaGetSymbolAddress((void**)&p_ffn,    g_ffn);
    cudaGetSymbolAddress((void**)&p_value,  g_value);

    // dynamic smem opt-ins (idempotent, non-stream host calls; capture-safe)
    cudaFuncSetAttribute(attn_kernel,
                         cudaFuncAttributeMaxDynamicSharedMemorySize, ATTN_SMEM);
    cudaFuncSetAttribute(gemm_tf32<0,0>,
                         cudaFuncAttributeMaxDynamicSharedMemorySize, GEMM_SMEM);
    cudaFuncSetAttribute(gemm_tf32<0,1>,
                         cudaFuncAttributeMaxDynamicSharedMemorySize, GEMM_SMEM);
    cudaFuncSetAttribute(gemm_tf32<1,0>,
                         cudaFuncAttributeMaxDynamicSharedMemorySize, GEMM_SMEM);

    const int M    = MROWS;                  // 4800
    const int GM   = (M + 63) / 64;          // 75 row-tiles
    const int GMC  = (MCH + 63) / 64;        // 1247 row-tiles per value chunk

    // ---- ONE side stream (memory-clean, R12/R15-proven); DisableTiming
    //      events. s1 order: vp -> value chunks 0..3 -> (wait ln2) -> aw.
    cudaStream_t s1;
    cudaStreamCreateWithFlags(&s1, cudaStreamNonBlocking);
    cudaEvent_t e_fork, e_vp, e_ln2, e_aw, e_vc[VCHUNKS];
    cudaEventCreateWithFlags(&e_fork, cudaEventDisableTiming);
    cudaEventCreateWithFlags(&e_vp,   cudaEventDisableTiming);
    cudaEventCreateWithFlags(&e_ln2,  cudaEventDisableTiming);
    cudaEventCreateWithFlags(&e_aw,   cudaEventDisableTiming);
    for (int c = 0; c < VCHUNKS; c++)
        cudaEventCreateWithFlags(&e_vc[c], cudaEventDisableTiming);

    cudaEventRecord(e_fork, 0);
    cudaStreamWaitEvent(s1, e_fork, 0);

    // s1: vp GEMM first (attn needs it early), then value GEMM in 4 chunks.
    gemm_tf32<0,0><<<dim3(2, GM), 256, GEMM_SMEM, s1>>>(
        tgt, w_in + 512 * 256, b_in + 512, p_vp, M, 256, 256);
    cudaEventRecord(e_vp, s1);
    for (int c = 0; c < VCHUNKS; c++) {
        gemm_tf32<0,1><<<dim3(2, GMC), 256, GEMM_SMEM, s1>>>(
            src + (size_t)c * MCH * 256, w_v, b_v,
            p_value + (size_t)c * MCH * 256, MCH, 256, 256);
        cudaEventRecord(e_vc[c], s1);
    }

    // ---- main stream: add -> qk GEMM -> attn (joins vp) ----
    add_kernel<<<(M * 256 + 255) / 256, 256>>>(tgt, qpos, p_q, M * 256);
    gemm_tf32<0,0><<<dim3(4, GM), 256, GEMM_SMEM>>>(p_q, w_in, b_in, p_qk, M, 512, 256);
    cudaStreamWaitEvent(0, e_vp, 0);
    attn_kernel<<<dim3(128, 3), 256, ATTN_SMEM>>>(p_qk, p_vp, p_sa);
    gemm_tf32<0,0><<<dim3(2, GM), 256, GEMM_SMEM>>>(p_sa, w_out, b_out, p_proj, M, 256, 256);
    ln_res<<<600, 256>>>(tgt, p_proj, gn2, bn2, qpos, p_tgt2, p_query2);
    cudaEventRecord(e_ln2, 0);

    // ---- off GEMM on main, aw GEMM on s1 (both consume query2) ----
    cudaStreamWaitEvent(s1, e_ln2, 0);
    gemm_tf32<0,0><<<dim3(1, GM), 256, GEMM_SMEM, s1>>>(p_query2, w_aw, b_aw, p_awl, M, 128, 256);
    cudaEventRecord(e_aw, s1);
    gemm_tf32<0,0><<<dim3(2, GM), 256, GEMM_SMEM>>>(p_query2, w_off, b_off, p_off, M, 256, 256);
    cudaStreamWaitEvent(0, e_aw, 0);
    locaw_kernel<<<4800, 128>>>(p_off, p_awl, refp, out_loc, out_aw);

    // ---- pipelined join: sampler chunk c waits only for value chunk c ----
    for (int c = 0; c < VCHUNKS; c++) {
        cudaStreamWaitEvent(0, e_vc[c], 0);
        sample_kernel<<<MROWS / VCHUNKS, 256>>>(
            p_value, out_loc, out_aw, p_cain, c * (MROWS / VCHUNKS));
    }
    gemm_tf32<0,0><<<dim3(2, GM), 256, GEMM_SMEM>>>(p_cain, w_o, b_o, p_proj, M, 256, 256);
    ln_res<<<600, 256>>>(p_tgt2, p_proj, gn1, bn1, nullptr, p_tgt3, nullptr);

    // ---- FFN ----
    gemm_tf32<1,0><<<dim3(8, GM), 256, GEMM_SMEM>>>(p_tgt3, w1, b1, p_ffn, M, 1024, 256);
    gemm_tf32<0,0><<<dim3(2, GM), 256, GEMM_SMEM>>>(p_ffn, w2, b2, p_proj, M, 256, 1024);
    ln_res<<<600, 256>>>(p_tgt3, p_proj, gn3, bn3, nullptr, out_tgt, nullptr);
}

// round 17
// speedup vs baseline: 1.0453x; 1.0453x over previous
#include <cuda_runtime.h>
#include <cuda_fp16.h>
#include <math.h>
#include <stdint.h>

#define B_      16
#define NQ_     300
#define C_      256
#define H_      8
#define L_      4
#define P_      4
#define DH_     32
#define DFFN_   1024
#define LEN_IN_ 19947
#define MROWS   (B_*NQ_)        // 4800
#define MVAL    (B_*LEN_IN_)    // 319152
#define VCHUNKS 4
#define BPC     (B_/VCHUNKS)    // 4 batches per chunk
#define MCH     (BPC*LEN_IN_)   // 79788 rows per value chunk

// ---------------- scratch (device globals; no allocation allowed) ----------
__device__ float  g_q     [MROWS*C_];
__device__ float  g_qk    [MROWS*2*C_];
__device__ float  g_vp    [MROWS*C_];
__device__ float  g_sa    [MROWS*C_];
__device__ float  g_proj  [MROWS*C_];
__device__ float  g_tgt2  [MROWS*C_];
__device__ float  g_query2[MROWS*C_];
__device__ float  g_off   [MROWS*C_];
__device__ float  g_awl   [MROWS*128];
__device__ float  g_cain  [MROWS*C_];
__device__ float  g_tgt3  [MROWS*C_];
__device__ float  g_ffn   [MROWS*DFFN_];
__device__ __half g_value [81702912];   // MVAL * 256 halfs = 163 MB

// ===========================================================================
// tf32 tensor-core NT GEMM v3: BM=64, BN=128, 3-stage cp.async ring.
// (used for all small/medium GEMMs)
// ===========================================================================
#define GEMM_ASTG  (64 * 36)
#define GEMM_WSTG  (128 * 36)
#define GEMM_STG   (GEMM_ASTG + GEMM_WSTG)
#define GEMM_SMEM  (3 * GEMM_STG * 4)               // 82944 B

__device__ __forceinline__ void cp_async16(uint32_t daddr, const void* src, int sz) {
    asm volatile("cp.async.cg.shared.global [%0], [%1], 16, %2;"
                 :: "r"(daddr), "l"(src), "r"(sz));
}
__device__ __forceinline__ void cp_commit() {
    asm volatile("cp.async.commit_group;");
}
template<int N>
__device__ __forceinline__ void cp_wait() {
    asm volatile("cp.async.wait_group %0;" :: "n"(N));
}

template<int RELU, int HOUT>
__global__ __launch_bounds__(256)
void gemm_tf32(const float* __restrict__ A, const float* __restrict__ W,
               const float* __restrict__ bias, void* __restrict__ Cv,
               int M, int N, int K)
{
    extern __shared__ __align__(16) uint32_t gsm[];

    const int tid  = threadIdx.x;
    const int lane = tid & 31;
    const int warp = tid >> 5;
    const int wm   = warp >> 2;
    const int wn   = warp & 3;
    const int bm   = blockIdx.y * 64;
    const int bn   = blockIdx.x * 128;

    const int srow = tid >> 3;
    const int sk4  = (tid & 7) * 4;

    float acc[2][4][4];
#pragma unroll
    for (int i = 0; i < 2; i++)
#pragma unroll
        for (int j = 0; j < 4; j++)
#pragma unroll
            for (int r = 0; r < 4; r++) acc[i][j][r] = 0.f;

    const int grp = lane >> 2;
    const int qid = lane & 3;

    const int KT = K >> 5;

    auto prefetch = [&](int s, int kt) {
        int k0 = kt * 32;
        uint32_t abase = __cvta_generic_to_shared(gsm + s * GEMM_STG);
        uint32_t wbase = abase + GEMM_ASTG * 4;
#pragma unroll
        for (int it = 0; it < 2; it++) {
            int row = srow + it * 32;
            int gr = bm + row;
            cp_async16(abase + (row * 36 + sk4) * 4,
                       A + (size_t)gr * K + k0 + sk4, (gr < M) ? 16 : 0);
        }
#pragma unroll
        for (int it = 0; it < 4; it++) {
            int row = srow + it * 32;
            int gw = bn + row;
            cp_async16(wbase + (row * 36 + sk4) * 4,
                       W + (size_t)gw * K + k0 + sk4, 16);
        }
        cp_commit();
    };

    prefetch(0, 0);
    if (KT > 1) prefetch(1, 1);

    int stage = 0;
    for (int kt = 0; kt < KT; kt++) {
        if (kt + 2 < KT) {
            prefetch((stage + 2) % 3, kt + 2);
            cp_wait<2>();
        } else if (kt + 1 < KT) {
            cp_wait<1>();
        } else {
            cp_wait<0>();
        }
        __syncthreads();

        const uint32_t* Asl = gsm + stage * GEMM_STG;
        const uint32_t* Wsl = Asl + GEMM_ASTG;
#pragma unroll
        for (int ks = 0; ks < 4; ks++) {
            const int kc = ks * 8 + qid;
            uint32_t af[2][4];
#pragma unroll
            for (int i = 0; i < 2; i++) {
                int mb = wm * 32 + i * 16 + grp;
                af[i][0] = Asl[mb * 36 + kc];
                af[i][1] = Asl[(mb + 8) * 36 + kc];
                af[i][2] = Asl[mb * 36 + kc + 4];
                af[i][3] = Asl[(mb + 8) * 36 + kc + 4];
            }
            uint32_t bf[4][2];
#pragma unroll
            for (int j = 0; j < 4; j++) {
                int nb = wn * 32 + j * 8 + grp;
                bf[j][0] = Wsl[nb * 36 + kc];
                bf[j][1] = Wsl[nb * 36 + kc + 4];
            }
#pragma unroll
            for (int i = 0; i < 2; i++)
#pragma unroll
                for (int j = 0; j < 4; j++) {
                    asm volatile(
                        "mma.sync.aligned.m16n8k8.row.col.f32.tf32.tf32.f32 "
                        "{%0,%1,%2,%3}, {%4,%5,%6,%7}, {%8,%9}, {%0,%1,%2,%3};"
                        : "+f"(acc[i][j][0]), "+f"(acc[i][j][1]),
                          "+f"(acc[i][j][2]), "+f"(acc[i][j][3])
                        : "r"(af[i][0]), "r"(af[i][1]), "r"(af[i][2]), "r"(af[i][3]),
                          "r"(bf[j][0]), "r"(bf[j][1]));
                }
        }
        __syncthreads();
        stage = (stage + 1) % 3;
    }

    // ---- epilogue ----
    float*  Cf = (float*)Cv;
    __half* Ch = (__half*)Cv;
#pragma unroll
    for (int j = 0; j < 4; j++) {
        int cc = bn + wn * 32 + j * 8 + qid * 2;
        float b0 = bias[cc], b1 = bias[cc + 1];
#pragma unroll
        for (int i = 0; i < 2; i++) {
            int r0 = bm + wm * 32 + i * 16 + grp;
            float v0 = acc[i][j][0] + b0;
            float v1 = acc[i][j][1] + b1;
            float v2 = acc[i][j][2] + b0;
            float v3 = acc[i][j][3] + b1;
            if (RELU) {
                v0 = fmaxf(v0, 0.f); v1 = fmaxf(v1, 0.f);
                v2 = fmaxf(v2, 0.f); v3 = fmaxf(v3, 0.f);
            }
            if (HOUT) {
                if (r0 < M)
                    *(__half2*)(Ch + (size_t)r0 * N + cc) = __floats2half2_rn(v0, v1);
                if (r0 + 8 < M)
                    *(__half2*)(Ch + (size_t)(r0 + 8) * N + cc) = __floats2half2_rn(v2, v3);
            } else {
                if (r0 < M)
                    *(float2*)(Cf + (size_t)r0 * N + cc) = make_float2(v0, v1);
                if (r0 + 8 < M)
                    *(float2*)(Cf + (size_t)(r0 + 8) * N + cc) = make_float2(v2, v3);
            }
        }
    }
}

// ===========================================================================
// fp16 tensor-core NT GEMM for the value projection.
// A fp32 (converted in staging), W fp32 (converted), C fp16.
// BM=64, BN=128, BK=32, 256 threads, warp tile 32x32, m16n8k16 mma,
// ldmatrix.x4 fragment loads, 2-stage smem, register-buffered staging.
// Row pad 40 halves (80 B): ldmatrix rows step 5 super-banks -> conflict-free.
// ===========================================================================
#define F16_LDA   40
#define F16_ASTG  (64 * F16_LDA)     // halves
#define F16_WSTG  (128 * F16_LDA)
#define F16_STGH  (F16_ASTG + F16_WSTG)     // 7680 halves/stage
#define F16_SMEM  (2 * F16_STGH * 2)        // 30720 B

__device__ __forceinline__ uint32_t f2h2(float a, float b) {
    __half2 h = __floats2half2_rn(a, b);
    return *reinterpret_cast<uint32_t*>(&h);
}
__device__ __forceinline__ void ldsm4(uint32_t& r0, uint32_t& r1,
                                      uint32_t& r2, uint32_t& r3, uint32_t addr) {
    asm volatile("ldmatrix.sync.aligned.m8n8.x4.shared.b16 {%0,%1,%2,%3}, [%4];"
                 : "=r"(r0), "=r"(r1), "=r"(r2), "=r"(r3) : "r"(addr));
}

__global__ __launch_bounds__(256)
void gemm_f16v(const float* __restrict__ A, const float* __restrict__ W,
               const float* __restrict__ bias, __half* __restrict__ C,
               int M, int N, int K)
{
    extern __shared__ __align__(16) __half hsm[];
    const int tid  = threadIdx.x;
    const int lane = tid & 31;
    const int warp = tid >> 5;
    const int wm   = warp >> 2;
    const int wn   = warp & 3;
    const int bm   = blockIdx.y * 64;
    const int bn   = blockIdx.x * 128;
    const int grp  = lane >> 2;
    const int qid  = lane & 3;

    // staging map: A ids 0..255 (row=t>>2, c8=t&3); W ids 0..511 (t, t+256)
    const int arow = tid >> 2, ac8 = tid & 3;

    float abuf[8], wbuf[16];
    auto ldg_stage = [&](int kt) {
        int k0 = kt * 32;
        const float* ap = A + (size_t)(bm + arow) * K + k0 + ac8 * 8;
        bool aok = (bm + arow) < M;
        float4 t0 = aok ? *(const float4*)(ap)     : make_float4(0.f, 0.f, 0.f, 0.f);
        float4 t1 = aok ? *(const float4*)(ap + 4) : make_float4(0.f, 0.f, 0.f, 0.f);
        abuf[0]=t0.x; abuf[1]=t0.y; abuf[2]=t0.z; abuf[3]=t0.w;
        abuf[4]=t1.x; abuf[5]=t1.y; abuf[6]=t1.z; abuf[7]=t1.w;
#pragma unroll
        for (int i = 0; i < 2; i++) {
            int id = tid + i * 256;
            int row = id >> 2, c8 = id & 3;
            const float* wp = W + (size_t)(bn + row) * K + k0 + c8 * 8;
            float4 u0 = *(const float4*)(wp);
            float4 u1 = *(const float4*)(wp + 4);
            wbuf[i*8+0]=u0.x; wbuf[i*8+1]=u0.y; wbuf[i*8+2]=u0.z; wbuf[i*8+3]=u0.w;
            wbuf[i*8+4]=u1.x; wbuf[i*8+5]=u1.y; wbuf[i*8+6]=u1.z; wbuf[i*8+7]=u1.w;
        }
    };
    auto sts_stage = [&](int s) {
        __half* as = hsm + s * F16_STGH;
        __half* ws = as + F16_ASTG;
        uint4 ua;
        ua.x = f2h2(abuf[0], abuf[1]); ua.y = f2h2(abuf[2], abuf[3]);
        ua.z = f2h2(abuf[4], abuf[5]); ua.w = f2h2(abuf[6], abuf[7]);
        *(uint4*)(as + arow * F16_LDA + ac8 * 8) = ua;
#pragma unroll
        for (int i = 0; i < 2; i++) {
            int id = tid + i * 256;
            int row = id >> 2, c8 = id & 3;
            uint4 uw;
            uw.x = f2h2(wbuf[i*8+0], wbuf[i*8+1]); uw.y = f2h2(wbuf[i*8+2], wbuf[i*8+3]);
            uw.z = f2h2(wbuf[i*8+4], wbuf[i*8+5]); uw.w = f2h2(wbuf[i*8+6], wbuf[i*8+7]);
            *(uint4*)(ws + row * F16_LDA + c8 * 8) = uw;
        }
    };

    float acc[2][4][4];
#pragma unroll
    for (int i = 0; i < 2; i++)
#pragma unroll
        for (int j = 0; j < 4; j++)
#pragma unroll
            for (int r = 0; r < 4; r++) acc[i][j][r] = 0.f;

    const int KT = K >> 5;              // 8 for K=256
    const int tile = lane >> 3, rin = lane & 7;

    ldg_stage(0);
    sts_stage(0);
    __syncthreads();

    for (int kt = 0; kt < KT; kt++) {
        if (kt + 1 < KT) ldg_stage(kt + 1);

        const int s = kt & 1;
        const __half* as = hsm + s * F16_STGH;
        const __half* ws = as + F16_ASTG;
        uint32_t abase = __cvta_generic_to_shared(as);
        uint32_t wbase = __cvta_generic_to_shared(ws);

#pragma unroll
        for (int ks = 0; ks < 2; ks++) {       // two k16 steps in BK=32
            const int kc = ks * 16;
            uint32_t a[2][4];
#pragma unroll
            for (int i = 0; i < 2; i++) {
                int mrow = wm * 32 + i * 16 + ((tile & 1) ? 8 : 0) + rin;
                int kk   = kc + ((tile >> 1) ? 8 : 0);
                ldsm4(a[i][0], a[i][1], a[i][2], a[i][3],
                      abase + (mrow * F16_LDA + kk) * 2);
            }
            uint32_t b[4][2];
#pragma unroll
            for (int jj = 0; jj < 2; jj++) {
                int nrow = wn * 32 + jj * 16 + ((tile >> 1) ? 8 : 0) + rin;
                int kk   = kc + ((tile & 1) ? 8 : 0);
                ldsm4(b[jj*2][0], b[jj*2][1], b[jj*2+1][0], b[jj*2+1][1],
                      wbase + (nrow * F16_LDA + kk) * 2);
            }
#pragma unroll
            for (int i = 0; i < 2; i++)
#pragma unroll
                for (int j = 0; j < 4; j++) {
                    asm volatile(
                        "mma.sync.aligned.m16n8k16.row.col.f32.f16.f16.f32 "
                        "{%0,%1,%2,%3}, {%4,%5,%6,%7}, {%8,%9}, {%0,%1,%2,%3};"
                        : "+f"(acc[i][j][0]), "+f"(acc[i][j][1]),
                          "+f"(acc[i][j][2]), "+f"(acc[i][j][3])
                        : "r"(a[i][0]), "r"(a[i][1]), "r"(a[i][2]), "r"(a[i][3]),
                          "r"(b[j][0]), "r"(b[j][1]));
                }
        }
        if (kt + 1 < KT) {
            sts_stage((kt + 1) & 1);
            __syncthreads();
        }
    }

    // ---- epilogue (fp16 out) ----
#pragma unroll
    for (int j = 0; j < 4; j++) {
        int cc = bn + wn * 32 + j * 8 + qid * 2;
        float b0 = bias[cc], b1 = bias[cc + 1];
#pragma unroll
        for (int i = 0; i < 2; i++) {
            int r0 = bm + wm * 32 + i * 16 + grp;
            if (r0 < M)
                *(__half2*)(C + (size_t)r0 * N + cc) =
                    __floats2half2_rn(acc[i][j][0] + b0, acc[i][j][1] + b1);
            if (r0 + 8 < M)
                *(__half2*)(C + (size_t)(r0 + 8) * N + cc) =
                    __floats2half2_rn(acc[i][j][2] + b0, acc[i][j][3] + b1);
        }
    }
}

// ---------------- elementwise add -----------------------------------------
__global__ void add_kernel(const float* __restrict__ a, const float* __restrict__ b,
                           float* __restrict__ o, int n)
{
    int i = blockIdx.x * blockDim.x + threadIdx.x;
    if (i < n) o[i] = a[i] + b[i];
}

// ---------------- fused self-attention v6: 2 queries/warp, no-shfl PV ------
#define ATTN_KS_   (300*36)
#define ATTN_VT_   (32*300)
#define ATTN_WS_   (16*304)
#define ATTN_SMEM  ((ATTN_KS_ + ATTN_VT_ + ATTN_WS_) * 4)   // 101056 B
__global__ __launch_bounds__(256)
void attn_kernel(const float* __restrict__ qk, const float* __restrict__ vp,
                 float* __restrict__ sa)
{
    extern __shared__ float smem[];
    float* Ks = smem;
    float* Vt = smem + ATTN_KS_;
    float* Wb = smem + ATTN_KS_ + ATTN_VT_;

    int bh = blockIdx.x;
    int b = bh >> 3, h = bh & 7;
    int qc = blockIdx.y;
    int wid = threadIdx.x >> 5, lane = threadIdx.x & 31;
    const float scale = 0.1767766952966369f;
    const float* kbase = qk + (size_t)b * NQ_ * 512 + 256 + h * 32;
    const float* vbase = vp + (size_t)b * NQ_ * 256 + h * 32;

    for (int idx = threadIdx.x; idx < NQ_ * 32; idx += 256) {
        int row = idx >> 5, d = idx & 31;
        Ks[row * 36 + d]  = kbase[(size_t)row * 512 + d];
        Vt[d * 300 + row] = vbase[(size_t)row * 256 + d];
    }
    __syncthreads();

    float* wsp0 = Wb + (wid * 2) * 304;
    float* wsp1 = wsp0 + 304;
    const float* vtp = Vt + lane * 300;

    const int q_end = qc * 100 + 100;
    for (int q0 = qc * 100 + wid * 2; q0 < q_end; q0 += 16) {
        const float* qrow0 = qk + (size_t)(b * NQ_ + q0) * 512 + h * 32;
        const float* qrow1 = qrow0 + 512;
        float qr0[32], qr1[32];
#pragma unroll
        for (int i = 0; i < 8; i++) {
            float4 t0 = *(const float4*)(qrow0 + i * 4);
            float4 t1 = *(const float4*)(qrow1 + i * 4);
            qr0[i*4] = t0.x; qr0[i*4+1] = t0.y; qr0[i*4+2] = t0.z; qr0[i*4+3] = t0.w;
            qr1[i*4] = t1.x; qr1[i*4+1] = t1.y; qr1[i*4+2] = t1.z; qr1[i*4+3] = t1.w;
        }
        float w0reg[10], w1reg[10];
#pragma unroll
        for (int kb = 0; kb < 10; kb++) {
            int k = kb * 32 + lane;
            float s0 = -1e30f, s1 = -1e30f;
            if (k < NQ_) {
                s0 = 0.f; s1 = 0.f;
                const float* kr = Ks + k * 36;
#pragma unroll
                for (int i = 0; i < 8; i++) {
                    float4 t = *(const float4*)(kr + i * 4);
                    s0 += qr0[i*4]*t.x + qr0[i*4+1]*t.y + qr0[i*4+2]*t.z + qr0[i*4+3]*t.w;
                    s1 += qr1[i*4]*t.x + qr1[i*4+1]*t.y + qr1[i*4+2]*t.z + qr1[i*4+3]*t.w;
                }
                s0 *= scale; s1 *= scale;
            }
            w0reg[kb] = s0; w1reg[kb] = s1;
        }
        float m0 = -1e30f, m1 = -1e30f;
#pragma unroll
        for (int kb = 0; kb < 10; kb++) {
            m0 = fmaxf(m0, w0reg[kb]);
            m1 = fmaxf(m1, w1reg[kb]);
        }
#pragma unroll
        for (int off = 16; off; off >>= 1) {
            m0 = fmaxf(m0, __shfl_xor_sync(0xffffffffu, m0, off));
            m1 = fmaxf(m1, __shfl_xor_sync(0xffffffffu, m1, off));
        }
        float ss0 = 0.f, ss1 = 0.f;
#pragma unroll
        for (int kb = 0; kb < 10; kb++) {
            float e0 = __expf(w0reg[kb] - m0);
            float e1 = __expf(w1reg[kb] - m1);
            w0reg[kb] = e0; w1reg[kb] = e1;
            ss0 += e0; ss1 += e1;
        }
#pragma unroll
        for (int off = 16; off; off >>= 1) {
            ss0 += __shfl_xor_sync(0xffffffffu, ss0, off);
            ss1 += __shfl_xor_sync(0xffffffffu, ss1, off);
        }
        float inv0 = 1.f / ss0, inv1 = 1.f / ss1;

#pragma unroll
        for (int kb = 0; kb < 10; kb++) {
            int kk = kb * 32 + lane;
            if (kk < NQ_) {
                wsp0[kk] = w0reg[kb] * inv0;
                wsp1[kk] = w1reg[kb] * inv1;
            }
        }
        __syncwarp();

        float a00 = 0.f, a01 = 0.f, a02 = 0.f, a03 = 0.f;
        float a10 = 0.f, a11 = 0.f, a12 = 0.f, a13 = 0.f;
#pragma unroll
        for (int k = 0; k < 300; k += 4) {
            float4 v  = *(const float4*)(vtp + k);
            float4 w0 = *(const float4*)(wsp0 + k);
            float4 w1 = *(const float4*)(wsp1 + k);
            a00 += w0.x * v.x; a01 += w0.y * v.y;
            a02 += w0.z * v.z; a03 += w0.w * v.w;
            a10 += w1.x * v.x; a11 += w1.y * v.y;
            a12 += w1.z * v.z; a13 += w1.w * v.w;
        }
        float acc0 = (a00 + a01) + (a02 + a03);
        float acc1 = (a10 + a11) + (a12 + a13);
        sa[(size_t)(b * NQ_ + q0) * 256 + h * 32 + lane]     = acc0;
        sa[(size_t)(b * NQ_ + q0 + 1) * 256 + h * 32 + lane] = acc1;
        __syncwarp();
    }
}

// ---------------- residual + LayerNorm (warp per row of 256) --------------
__global__ __launch_bounds__(256)
void ln_res(const float* __restrict__ x, const float* __restrict__ y,
            const float* __restrict__ gam, const float* __restrict__ bet,
            const float* __restrict__ qpos, float* __restrict__ out,
            float* __restrict__ qout)
{
    int w = threadIdx.x >> 5, lane = threadIdx.x & 31;
    int row = blockIdx.x * 8 + w;
    if (row >= MROWS) return;
    const float* xr = x + (size_t)row * 256;
    const float* yr = y + (size_t)row * 256;
    float v[8];
#pragma unroll
    for (int i = 0; i < 8; i++) { int c = i*32 + lane; v[i] = xr[c] + yr[c]; }
    float s = 0.f;
#pragma unroll
    for (int i = 0; i < 8; i++) s += v[i];
#pragma unroll
    for (int off = 16; off; off >>= 1) s += __shfl_xor_sync(0xffffffffu, s, off);
    float mean = s * (1.f / 256.f);
    float vs = 0.f;
#pragma unroll
    for (int i = 0; i < 8; i++) { float d = v[i] - mean; vs += d * d; }
#pragma unroll
    for (int off = 16; off; off >>= 1) vs += __shfl_xor_sync(0xffffffffu, vs, off);
    float rstd = rsqrtf(vs * (1.f / 256.f) + 1e-5f);
#pragma unroll
    for (int i = 0; i < 8; i++) {
        int c = i*32 + lane;
        float o = (v[i] - mean) * rstd * gam[c] + bet[c];
        out[(size_t)row * 256 + c] = o;
        if (qout) qout[(size_t)row * 256 + c] = o + qpos[(size_t)row * 256 + c];
    }
}

// ---------------- loc + attention-weight softmax (writes outputs 2 & 3) ---
__global__ __launch_bounds__(128)
void locaw_kernel(const float* __restrict__ off, const float* __restrict__ awl,
                  const float* __restrict__ refp, float* __restrict__ out_loc,
                  float* __restrict__ out_aw)
{
    int bq = blockIdx.x;
    int tid = threadIdx.x;
    int h = tid >> 4, lp = tid & 15, l = lp >> 2;

    float logit = awl[(size_t)bq * 128 + tid];
    float m = logit;
#pragma unroll
    for (int s = 8; s; s >>= 1)
        m = fmaxf(m, __shfl_xor_sync(0xffffffffu, m, s, 16));
    float e = __expf(logit - m);
    float ssum = e;
#pragma unroll
    for (int s = 8; s; s >>= 1)
        ssum += __shfl_xor_sync(0xffffffffu, ssum, s, 16);
    out_aw[(size_t)bq * 128 + tid] = e / ssum;

    float ox = off[(size_t)bq * 256 + h * 32 + lp * 2];
    float oy = off[(size_t)bq * 256 + h * 32 + lp * 2 + 1];
    float rx = refp[(size_t)bq * 8 + l * 2];
    float ry = refp[(size_t)bq * 8 + l * 2 + 1];
    float wlx = (l == 0) ? 150.f : (l == 1) ? 75.f : (l == 2) ? 38.f : 19.f;
    float wly = (l == 0) ? 100.f : (l == 1) ? 50.f : (l == 2) ? 25.f : 13.f;
    out_loc[((size_t)bq * 128 + tid) * 2]     = rx + ox / wlx;
    out_loc[((size_t)bq * 128 + tid) * 2 + 1] = ry + oy / wly;
}

// ---------------- deformable bilinear sampling (fp16 value, chunked) ------
__global__ __launch_bounds__(256)
void sample_kernel(const __half* __restrict__ value, const float* __restrict__ loc,
                   const float* __restrict__ aw, float* __restrict__ cain, int blk0)
{
    int widx = (blockIdx.x + blk0) * 8 + (threadIdx.x >> 5);
    int lane = threadIdx.x & 31;
    int h = widx & 7;
    int bq = widx >> 3;
    int b = bq / NQ_;

    const int HlA[4] = {100, 50, 25, 13};
    const int WlA[4] = {150, 75, 38, 19};
    const int stA[4] = {0, 15000, 18750, 19700};

    const float* locp = loc + (size_t)widx * 32;
    const float* awp  = aw  + (size_t)widx * 16;
    const __half* vb  = value + (size_t)b * LEN_IN_ * 256 + h * 32 + lane;

    float acc = 0.f;
#pragma unroll
    for (int l = 0; l < 4; l++) {
        const int Hl = HlA[l], Wl = WlA[l];
        const __half* base = vb + (size_t)stA[l] * 256;
#pragma unroll
        for (int p = 0; p < 4; p++) {
            int lp = l * 4 + p;
            float wgt = awp[lp];
            float lx = locp[lp * 2], ly = locp[lp * 2 + 1];
            float ix = lx * (float)Wl - 0.5f;
            float iy = ly * (float)Hl - 0.5f;
            float x0f = floorf(ix), y0f = floorf(iy);
            float wx = ix - x0f, wy = iy - y0f;
            int x0 = (int)x0f, y0 = (int)y0f;
            int x1 = x0 + 1, y1 = y0 + 1;
            bool vx0 = (x0 >= 0) && (x0 < Wl);
            bool vx1 = (x1 >= 0) && (x1 < Wl);
            bool vy0 = (y0 >= 0) && (y0 < Hl);
            bool vy1 = (y1 >= 0) && (y1 < Hl);
            float v00 = 0.f, v10 = 0.f, v01 = 0.f, v11 = 0.f;
            if (vx0 && vy0) v00 = __half2float(base[(size_t)(y0 * Wl + x0) * 256]);
            if (vx1 && vy0) v10 = __half2float(base[(size_t)(y0 * Wl + x1) * 256]);
            if (vx0 && vy1) v01 = __half2float(base[(size_t)(y1 * Wl + x0) * 256]);
            if (vx1 && vy1) v11 = __half2float(base[(size_t)(y1 * Wl + x1) * 256]);
            float s = (1.f - wx) * (1.f - wy) * v00 + wx * (1.f - wy) * v10
                    + (1.f - wx) * wy * v01 + wx * wy * v11;
            acc += wgt * s;
        }
    }
    cain[(size_t)bq * 256 + h * 32 + lane] = acc;
}

// ---------------------------------------------------------------------------
extern "C" void kernel_launch(void* const* d_in, const int* in_sizes, int n_in,
                              void* d_out, int out_size)
{
    const float* tgt   = (const float*)d_in[0];
    const float* qpos  = (const float*)d_in[1];
    const float* refp  = (const float*)d_in[2];
    const float* src   = (const float*)d_in[3];
    const float* w_in  = (const float*)d_in[7];
    const float* b_in  = (const float*)d_in[8];
    const float* w_out = (const float*)d_in[9];
    const float* b_out = (const float*)d_in[10];
    const float* gn2   = (const float*)d_in[11];
    const float* bn2   = (const float*)d_in[12];
    const float* w_v   = (const float*)d_in[13];
    const float* b_v   = (const float*)d_in[14];
    const float* w_off = (const float*)d_in[15];
    const float* b_off = (const float*)d_in[16];
    const float* w_aw  = (const float*)d_in[17];
    const float* b_aw  = (const float*)d_in[18];
    const float* w_o   = (const float*)d_in[19];
    const float* b_o   = (const float*)d_in[20];
    const float* gn1   = (const float*)d_in[21];
    const float* bn1   = (const float*)d_in[22];
    const float* w1    = (const float*)d_in[23];
    const float* b1    = (const float*)d_in[24];
    const float* w2    = (const float*)d_in[25];
    const float* b2    = (const float*)d_in[26];
    const float* gn3   = (const float*)d_in[27];
    const float* bn3   = (const float*)d_in[28];

    float* out_tgt = (float*)d_out;                    // B*NQ*C   = 1228800
    float* out_loc = out_tgt + 1228800;                // B*NQ*H*L*P*2 = 1228800
    float* out_aw  = out_loc + 1228800;                // B*NQ*H*L*P   = 614400

    float *p_q, *p_qk, *p_vp, *p_sa, *p_proj, *p_tgt2, *p_query2;
    float *p_off, *p_awl, *p_cain, *p_tgt3, *p_ffn;
    __half* p_value;
    cudaGetSymbolAddress((void**)&p_q,      g_q);
    cudaGetSymbolAddress((void**)&p_qk,     g_qk);
    cudaGetSymbolAddress((void**)&p_vp,     g_vp);
    cudaGetSymbolAddress((void**)&p_sa,     g_sa);
    cudaGetSymbolAddress((void**)&p_proj,   g_proj);
    cudaGetSymbolAddress((void**)&p_tgt2,   g_tgt2);
    cudaGetSymbolAddress((void**)&p_query2, g_query2);
    cudaGetSymbolAddress((void**)&p_off,    g_off);
    cudaGetSymbolAddress((void**)&p_awl,    g_awl);
    cudaGetSymbolAddress((void**)&p_cain,   g_cain);
    cudaGetSymbolAddress((void**)&p_tgt3,   g_tgt3);
    cudaGetSymbolAddress((void**)&p_ffn,    g_ffn);
    cudaGetSymbolAddress((void**)&p_value,  g_value);

    // dynamic smem opt-ins (idempotent, non-stream host calls; capture-safe)
    cudaFuncSetAttribute(attn_kernel,
                         cudaFuncAttributeMaxDynamicSharedMemorySize, ATTN_SMEM);
    cudaFuncSetAttribute(gemm_tf32<0,0>,
                         cudaFuncAttributeMaxDynamicSharedMemorySize, GEMM_SMEM);
    cudaFuncSetAttribute(gemm_tf32<1,0>,
                         cudaFuncAttributeMaxDynamicSharedMemorySize, GEMM_SMEM);
    cudaFuncSetAttribute(gemm_f16v,
                         cudaFuncAttributeMaxDynamicSharedMemorySize, F16_SMEM);

    const int M    = MROWS;                  // 4800
    const int GM   = (M + 63) / 64;          // 75 row-tiles
    const int GMC  = (MCH + 63) / 64;        // 1247 row-tiles per value chunk

    // ---- ONE side stream (memory-clean pattern); DisableTiming events.
    cudaStream_t s1;
    cudaStreamCreateWithFlags(&s1, cudaStreamNonBlocking);
    cudaEvent_t e_fork, e_vp, e_ln2, e_aw, e_vc[VCHUNKS];
    cudaEventCreateWithFlags(&e_fork, cudaEventDisableTiming);
    cudaEventCreateWithFlags(&e_vp,   cudaEventDisableTiming);
    cudaEventCreateWithFlags(&e_ln2,  cudaEventDisableTiming);
    cudaEventCreateWithFlags(&e_aw,   cudaEventDisableTiming);
    for (int c = 0; c < VCHUNKS; c++)
        cudaEventCreateWithFlags(&e_vc[c], cudaEventDisableTiming);

    cudaEventRecord(e_fork, 0);
    cudaStreamWaitEvent(s1, e_fork, 0);

    // s1: vp GEMM first (attn needs it early), then fp16 value GEMM chunks.
    gemm_tf32<0,0><<<dim3(2, GM), 256, GEMM_SMEM, s1>>>(
        tgt, w_in + 512 * 256, b_in + 512, p_vp, M, 256, 256);
    cudaEventRecord(e_vp, s1);
    for (int c = 0; c < VCHUNKS; c++) {
        gemm_f16v<<<dim3(2, GMC), 256, F16_SMEM, s1>>>(
            src + (size_t)c * MCH * 256, w_v, b_v,
            p_value + (size_t)c * MCH * 256, MCH, 256, 256);
        cudaEventRecord(e_vc[c], s1);
    }

    // ---- main stream: add -> qk GEMM -> attn (joins vp) ----
    add_kernel<<<(M * 256 + 255) / 256, 256>>>(tgt, qpos, p_q, M * 256);
    gemm_tf32<0,0><<<dim3(4, GM), 256, GEMM_SMEM>>>(p_q, w_in, b_in, p_qk, M, 512, 256);
    cudaStreamWaitEvent(0, e_vp, 0);
    attn_kernel<<<dim3(128, 3), 256, ATTN_SMEM>>>(p_qk, p_vp, p_sa);
    gemm_tf32<0,0><<<dim3(2, GM), 256, GEMM_SMEM>>>(p_sa, w_out, b_out, p_proj, M, 256, 256);
    ln_res<<<600, 256>>>(tgt, p_proj, gn2, bn2, qpos, p_tgt2, p_query2);
    cudaEventRecord(e_ln2, 0);

    // ---- off GEMM on main, aw GEMM on s1 (both consume query2) ----
    cudaStreamWaitEvent(s1, e_ln2, 0);
    gemm_tf32<0,0><<<dim3(1, GM), 256, GEMM_SMEM, s1>>>(p_query2, w_aw, b_aw, p_awl, M, 128, 256);
    cudaEventRecord(e_aw, s1);
    gemm_tf32<0,0><<<dim3(2, GM), 256, GEMM_SMEM>>>(p_query2, w_off, b_off, p_off, M, 256, 256);
    cudaStreamWaitEvent(0, e_aw, 0);
    locaw_kernel<<<4800, 128>>>(p_off, p_awl, refp, out_loc, out_aw);

    // ---- pipelined join: sampler chunk c waits only for value chunk c ----
    for (int c = 0; c < VCHUNKS; c++) {
        cudaStreamWaitEvent(0, e_vc[c], 0);
        sample_kernel<<<MROWS / VCHUNKS, 256>>>(
            p_value, out_loc, out_aw, p_cain, c * (MROWS / VCHUNKS));
    }
    gemm_tf32<0,0><<<dim3(2, GM), 256, GEMM_SMEM>>>(p_cain, w_o, b_o, p_proj, M, 256, 256);
    ln_res<<<600, 256>>>(p_tgt2, p_proj, gn1, bn1, nullptr, p_tgt3, nullptr);

    // ---- FFN ----
    gemm_tf32<1,0><<<dim3(8, GM), 256, GEMM_SMEM>>>(p_tgt3, w1, b1, p_ffn, M, 1024, 256);
    gemm_tf32<0,0><<<dim3(2, GM), 256, GEMM_SMEM>>>(p_ffn, w2, b2, p_proj, M, 256, 1024);
    ln_res<<<600, 256>>>(p_tgt3, p_proj, gn3, bn3, nullptr, out_tgt, nullptr);
}